// round 5
// baseline (speedup 1.0000x reference)
#include <cuda_runtime.h>
#include <math.h>

#define B_    32
#define S_    1024
#define IN_   1024
#define H_    1024
#define NCTA  128

typedef unsigned long long ull;

// ---------------- device scratch (no allocation allowed) ----------------
__device__ float    g_H[2][B_][H_];      // ping-pong hidden state
__device__ unsigned g_flags[4][32];      // per batch-group step flags
__device__ unsigned g_arrive;            // monotonic grid-barrier counter (replay-safe)

// ---------------- helpers ----------------
__device__ __forceinline__ unsigned ld_acq(const unsigned* p) {
    unsigned v;
    asm volatile("ld.global.acquire.gpu.u32 %0, [%1];" : "=r"(v) : "l"(p));
    return v;
}
__device__ __forceinline__ void st_rel(unsigned* p, unsigned v) {
    asm volatile("st.global.release.gpu.u32 [%0], %1;" :: "l"(p), "r"(v));
}
__device__ __forceinline__ unsigned atom_add_rel(unsigned* p, unsigned v) {
    unsigned old;
    asm volatile("atom.add.release.gpu.u32 %0, [%1], %2;" : "=r"(old) : "l"(p), "r"(v));
    return old;
}
__device__ __forceinline__ ull fma2(ull a, ull b, ull c) {
    ull d;
    asm("fma.rn.f32x2 %0, %1, %2, %3;" : "=l"(d) : "l"(a), "l"(b), "l"(c));
    return d;
}
__device__ __forceinline__ ull add2(ull a, ull b) {
    ull d;
    asm("add.rn.f32x2 %0, %1, %2;" : "=l"(d) : "l"(a), "l"(b));
    return d;
}
__device__ __forceinline__ ull pack2(float x) {
    ull d;
    asm("mov.b64 %0, {%1, %1};" : "=l"(d) : "f"(x));
    return d;
}
__device__ __forceinline__ void unpack2(ull v, float& lo, float& hi) {
    asm("mov.b64 {%0, %1}, %2;" : "=f"(lo), "=f"(hi) : "l"(v));
}
// accurate-enough tanh: 1 - 2/(exp2(2x*log2e)+1); abs err ~5e-7, saturates correctly
__device__ __forceinline__ float tanh_fast(float x) {
    float a = x * 2.88539008177792681472f;   // 2*log2(e)
    float e;
    asm("ex2.approx.f32 %0, %1;" : "=f"(e) : "f"(a));
    float d = e + 1.0f;
    float r;
    asm("rcp.approx.f32 %0, %1;" : "=f"(r) : "f"(d));
    return fmaf(-2.0f, r, 1.0f);
}

// ---------------- fused kernel ----------------
// SMEM: Ws [1024][34] (W_hh slice, k-major)  +  Hs [8][1024] (staged H rows).
// GEMM phase overlays its double-buffered tiles on the Hs region.
#define WS_STRIDE   34
#define WS_FLOATS   (H_ * WS_STRIDE)        // 34816
#define HS_FLOATS   (8 * H_)                // 8192
#define SMEM_BYTES  ((WS_FLOATS + HS_FLOATS) * 4)

extern __shared__ float smem_f[];

__global__ void __launch_bounds__(256, 1) fused_rnn_kernel(
    const float* __restrict__ X,     // [32, 1024, 1024]
    const float* __restrict__ Wxh,   // [1024, 1024]
    const float* __restrict__ Whh,   // [1024, 1024]
    const float* __restrict__ bias,  // [1024]
    float* __restrict__ out,         // [B,S,H] (+ [B,H] tail)
    int write_last)
{
    float* Ws = smem_f;                 // scan weights
    float* Hs = smem_f + WS_FLOATS;     // scan staged H / gemm buffers

    int tid = threadIdx.x;
    int cta = blockIdx.x;
    int bg  = cta >> 5;      // batch group 0..3
    int cg  = cta & 31;      // col group 0..31
    int b0  = bg * 8;
    int j0  = cg * 32;

    if (tid == 0) g_flags[bg][cg] = 0u;   // published by the grid barrier release

    // ================= PHASE 1: Xp = X @ W_xh + b (double-buffered SGEMM) ========
    {
        // buffers: As[buf][k][row] = Hs[buf*1024 + k*128 + row], Bs at Hs+2048
        float* AsB = Hs;
        float* BsB = Hs + 2048;

        int arow = tid >> 1;            // 0..127
        int acol = (tid & 1) * 4;       // 0 or 4
        int brl  = tid >> 5;            // 0..7
        int bc4  = (tid & 31) * 4;      // 0..124
        int ty   = tid >> 4;            // 0..15
        int tx   = tid & 15;            // 0..15

        for (int r = 0; r < 16; r++) {
            int tileid = cta * 16 + r;
            int bx = tileid & 7;
            int by = tileid >> 3;
            int brow = by * 128, bcol = bx * 128;

            const float* Aptr = X   + (size_t)(brow + arow) * IN_ + acol;
            const float* Bptr = Wxh + (size_t)brl * H_ + bcol + bc4;

            ull acc2[8][4];
#pragma unroll
            for (int i = 0; i < 8; i++)
#pragma unroll
                for (int j = 0; j < 4; j++) acc2[i][j] = 0ull;

            // prologue: slab 0 into buf 0
            {
                float4 a = *(const float4*)Aptr;
                float4 b = *(const float4*)Bptr;
                AsB[(acol + 0) * 128 + arow] = a.x;
                AsB[(acol + 1) * 128 + arow] = a.y;
                AsB[(acol + 2) * 128 + arow] = a.z;
                AsB[(acol + 3) * 128 + arow] = a.w;
                *(float4*)&BsB[brl * 128 + bc4] = b;
            }
            __syncthreads();

            int p = 0;
            for (int s = 0; s < 128; s++) {
                float4 an, bn;
                if (s < 127) {
                    an = *(const float4*)(Aptr + (s + 1) * 8);
                    bn = *(const float4*)(Bptr + (size_t)(s + 1) * 8 * H_);
                }
                const float* Asp = AsB + p * 1024;
                const float* Bsp = BsB + p * 1024;
#pragma unroll
                for (int k = 0; k < 8; k++) {
                    float ar[8];
                    *(float4*)(ar)     = *(const float4*)&Asp[k * 128 + ty * 4];
                    *(float4*)(ar + 4) = *(const float4*)&Asp[k * 128 + 64 + ty * 4];
                    ull br2[4];
                    br2[0] = *(const ull*)&Bsp[k * 128 + tx * 4];
                    br2[1] = *(const ull*)&Bsp[k * 128 + tx * 4 + 2];
                    br2[2] = *(const ull*)&Bsp[k * 128 + 64 + tx * 4];
                    br2[3] = *(const ull*)&Bsp[k * 128 + 64 + tx * 4 + 2];
                    ull ar2[8];
#pragma unroll
                    for (int i = 0; i < 8; i++) ar2[i] = pack2(ar[i]);
#pragma unroll
                    for (int i = 0; i < 8; i++)
#pragma unroll
                        for (int j = 0; j < 4; j++)
                            acc2[i][j] = fma2(ar2[i], br2[j], acc2[i][j]);
                }
                if (s < 127) {
                    float* Asn = AsB + (p ^ 1) * 1024;
                    float* Bsn = BsB + (p ^ 1) * 1024;
                    Asn[(acol + 0) * 128 + arow] = an.x;
                    Asn[(acol + 1) * 128 + arow] = an.y;
                    Asn[(acol + 2) * 128 + arow] = an.z;
                    Asn[(acol + 3) * 128 + arow] = an.w;
                    *(float4*)&Bsn[brl * 128 + bc4] = bn;
                }
                __syncthreads();
                p ^= 1;
            }

            // epilogue
            float4 bv0 = *(const float4*)&bias[bcol + tx * 4];
            float4 bv1 = *(const float4*)&bias[bcol + 64 + tx * 4];
            float bb[8] = {bv0.x, bv0.y, bv0.z, bv0.w, bv1.x, bv1.y, bv1.z, bv1.w};
#pragma unroll
            for (int i = 0; i < 8; i++) {
                int m = brow + ((i < 4) ? (ty * 4 + i) : (64 + ty * 4 + (i - 4)));
                float o[8];
                unpack2(acc2[i][0], o[0], o[1]);
                unpack2(acc2[i][1], o[2], o[3]);
                unpack2(acc2[i][2], o[4], o[5]);
                unpack2(acc2[i][3], o[6], o[7]);
                float4 o0, o1;
                o0.x = o[0] + bb[0]; o0.y = o[1] + bb[1];
                o0.z = o[2] + bb[2]; o0.w = o[3] + bb[3];
                o1.x = o[4] + bb[4]; o1.y = o[5] + bb[5];
                o1.z = o[6] + bb[6]; o1.w = o[7] + bb[7];
                *(float4*)&out[(size_t)m * H_ + bcol + tx * 4]      = o0;
                *(float4*)&out[(size_t)m * H_ + bcol + 64 + tx * 4] = o1;
            }
        }
    }

    // ---- preload W_hh slice while other CTAs finish gemm: Ws[k][j] = Whh[k][j0+j]
    {
        int j = tid & 31;
        for (int k = tid >> 5; k < H_; k += 8)
            Ws[k * WS_STRIDE + j] = Whh[(size_t)k * H_ + j0 + j];
    }

    // ---- grid barrier (monotonic epoch counter: safe under graph replay) ----
    if (tid == 0) {
        unsigned old = atom_add_rel(&g_arrive, 1u);
        unsigned target = (old / NCTA) * NCTA + NCTA;
        while (ld_acq(&g_arrive) < target) { }
    }
    __syncthreads();

    // ================= PHASE 2: recurrent scan ==================================
    int w    = tid >> 5, lane = tid & 31;
    int bhalf = w & 1;           // batches b0+[0..3] or b0+[4..7]
    int jt    = w >> 1;          // j-tile 0..3 (8 cols each)
    int ob = b0 + bhalf * 4 + ((lane >> 3) & 3);
    int oj = j0 + jt * 8 + (lane & 7);
    size_t out_idx0 = ((size_t)ob * S_) * H_ + oj;

    const unsigned* pollp = &g_flags[bg][tid >> 3];  // the flag covering this
                                                     // thread's staged columns
    const float* hpB = Hs + (bhalf * 4) * H_;
    const float* wpB = Ws + jt * 8;

    float val;
    // ---- step 0: H1 = tanh(Xp0) (H0 == 0, no matmul needed) ----
    {
        float xr = __ldcg(&out[out_idx0]);
        val = tanh_fast(xr);
        g_H[1][ob][oj] = val;
        __syncthreads();
        if (tid == 0) st_rel(&g_flags[bg][cg], 1u);
        out[out_idx0] = val;
    }

    for (int t = 1; t < S_; t++) {
        // prefetch this thread's Xp(t) early (DRAM latency hidden by poll+stage+fma)
        float xr = __ldcg(&out[out_idx0 + (size_t)t * H_]);

        // poll only the flag for the columns this thread stages
        while (ld_acq(pollp) < (unsigned)t) { }

        // stage H(t) rows b0..b0+7 into SMEM (thread's chunks all belong to pollp's producer)
        {
            const float4* Hsrc = (const float4*)(&g_H[t & 1][b0][0]);
            float4* Hdst = (float4*)Hs;
#pragma unroll
            for (int q = 0; q < 8; q++)
                Hdst[tid + q * 256] = __ldcg(Hsrc + tid + q * 256);
        }
        __syncthreads();

        // ---- per-warp full-k tile: 4 batches x 8 cols, k over lanes ----
        ull V[16];
#pragma unroll
        for (int v = 0; v < 16; v++) V[v] = 0ull;

#pragma unroll 4
        for (int i = 0; i < 32; i++) {
            int k = i * 32 + lane;
            ull h2[4], w2[4];
#pragma unroll
            for (int bb = 0; bb < 4; bb++) h2[bb] = pack2(hpB[bb * H_ + k]);
#pragma unroll
            for (int q = 0; q < 4; q++)
                w2[q] = *(const ull*)&wpB[k * WS_STRIDE + q * 2];
#pragma unroll
            for (int bb = 0; bb < 4; bb++)
#pragma unroll
                for (int q = 0; q < 4; q++)
                    V[bb * 4 + q] = fma2(h2[bb], w2[q], V[bb * 4 + q]);
        }

        // ---- in-warp split butterfly over 32 k-lanes (no SMEM, no extra sync) ----
        unsigned s;
        ull R8[8];
        s = lane & 16;
#pragma unroll
        for (int g = 0; g < 8; g++) {
            ull keep = s ? V[g + 8] : V[g];
            ull send = s ? V[g] : V[g + 8];
            R8[g] = add2(keep, __shfl_xor_sync(0xffffffffu, send, 16));
        }
        ull R4[4];
        s = lane & 8;
#pragma unroll
        for (int g = 0; g < 4; g++) {
            ull keep = s ? R8[g + 4] : R8[g];
            ull send = s ? R8[g] : R8[g + 4];
            R4[g] = add2(keep, __shfl_xor_sync(0xffffffffu, send, 8));
        }
        ull R2[2];
        s = lane & 4;
#pragma unroll
        for (int g = 0; g < 2; g++) {
            ull keep = s ? R4[g + 2] : R4[g];
            ull send = s ? R4[g] : R4[g + 2];
            R2[g] = add2(keep, __shfl_xor_sync(0xffffffffu, send, 4));
        }
        ull R1;
        s = lane & 2;
        {
            ull keep = s ? R2[1] : R2[0];
            ull send = s ? R2[0] : R2[1];
            R1 = add2(keep, __shfl_xor_sync(0xffffffffu, send, 2));
        }
        float fin;
        {
            float lo, hi;
            unpack2(R1, lo, hi);
            s = lane & 1;
            float keep = s ? hi : lo;
            float send = s ? lo : hi;
            fin = keep + __shfl_xor_sync(0xffffffffu, send, 1);
        }

        // ---- tail: tanh, publish H(t+1), release flag, then out store ----
        val = tanh_fast(fin + xr);
        g_H[(t + 1) & 1][ob][oj] = val;
        __syncthreads();
        if (tid == 0) st_rel(&g_flags[bg][cg], (unsigned)(t + 1));
        out[out_idx0 + (size_t)t * H_] = val;
    }

    if (write_last)
        out[(size_t)B_ * S_ * H_ + (size_t)ob * H_ + oj] = val;
}

// ---------------- launch ----------------
extern "C" void kernel_launch(void* const* d_in, const int* in_sizes, int n_in,
                              void* d_out, int out_size) {
    const float* X    = (const float*)d_in[0];
    const float* Wxh  = (const float*)d_in[1];
    const float* Whh  = (const float*)d_in[2];
    const float* bh   = (const float*)d_in[3];
    float* out        = (float*)d_out;

    cudaFuncSetAttribute(fused_rnn_kernel,
                         cudaFuncAttributeMaxDynamicSharedMemorySize,
                         SMEM_BYTES);
    int write_last = (out_size >= B_ * S_ * H_ + B_ * H_) ? 1 : 0;
    fused_rnn_kernel<<<NCTA, 256, SMEM_BYTES>>>(X, Wxh, Whh, bh, out, write_last);
}